// round 13
// baseline (speedup 1.0000x reference)
#include <cuda_runtime.h>
#include <math.h>

#define NP     4096
#define TOTAL  65536
#define ROWS   32
#define NB     256
#define LOV    (-5.0f)
#define HIV    (5.0f)
#define WBIN   ((HIV - LOV) / NB)
#define INVW   ((float)NB / (HIV - LOV))
#define PAD    2
#define WMIN   320
#define WCAPP  640                 // staged window cap in PAIRS (1280 pts, 20 KB)
#define BT     128
#define QPB    128
#define NBLK   (2 * TOTAL / QPB)   // 1024
#define FULLM  0xFFFFFFFFu

__device__ float4 g_sorted[2 * TOTAL];
__device__ int    g_binstart[ROWS][NB + 1];
__device__ float  g_partial[NBLK];

__device__ __forceinline__ int binof(float v) {
    int b = (int)((v - LOV) * INVW);
    return min(max(b, 0), NB - 1);
}

#define FMA2(d, a, bb, c) \
    asm("fma.rn.f32x2 %0, %1, %2, %3;" : "=l"(d) : "l"(a), "l"(bb), "l"(c))

__device__ __forceinline__ unsigned long long bcast2(float v) {
    unsigned long long r;
    unsigned u = __float_as_uint(v);
    asm("mov.b64 %0, {%1, %1};" : "=l"(r) : "r"(u));
    return r;
}

__device__ __forceinline__ void minacc2(float& mlo, float& mhi, unsigned long long t) {
    unsigned lo, hi;
    asm("mov.b64 {%0, %1}, %2;" : "=r"(lo), "=r"(hi) : "l"(t));
    mlo = fminf(mlo, __uint_as_float(lo));
    mhi = fminf(mhi, __uint_as_float(hi));
}

// One block per (tensor,batch) row: hist + scan + scatter, block-local.
__global__ __launch_bounds__(512) void prep_kernel(const float* __restrict__ x,
                                                   const float* __restrict__ y) {
    int row = blockIdx.x;
    const float* src = ((row >= 16) ? y : x) + (size_t)(row & 15) * NP * 3;
    __shared__ int h[NB];
    __shared__ int base[NB];
    __shared__ int cnt[NB];
    int tid = threadIdx.x;

    if (tid < NB) h[tid] = 0;
    __syncthreads();

    float2 r[12];
    const float2* s2 = (const float2*)(src + 24 * tid);
    #pragma unroll
    for (int i = 0; i < 12; i++) r[i] = s2[i];

    int bins[8];
    #pragma unroll
    for (int p = 0; p < 8; p++) {
        float vx = ((const float*)r)[3 * p];
        bins[p] = binof(vx);
        atomicAdd(&h[bins[p]], 1);
    }
    __syncthreads();

    int v = 0;
    if (tid < NB) { v = h[tid]; base[tid] = v; }
    __syncthreads();
    #pragma unroll
    for (int off = 1; off < NB; off <<= 1) {
        int t = 0;
        if (tid < NB && tid >= off) t = base[tid - off];
        __syncthreads();
        if (tid < NB) base[tid] += t;
        __syncthreads();
    }
    if (tid < NB) {
        int ex = base[tid] - v;
        g_binstart[row][tid] = ex;
        base[tid] = ex;
        cnt[tid] = 0;
        if (tid == NB - 1) g_binstart[row][NB] = ex + v;
    }
    __syncthreads();

    float4* dst = g_sorted + (size_t)row * NP;
    #pragma unroll
    for (int p = 0; p < 8; p++) {
        const float* f = (const float*)r + 3 * p;
        float a = f[0], c = f[1], d = f[2];
        int pos = base[bins[p]] + atomicAdd(&cnt[bins[p]], 1);
        dst[pos] = make_float4(a, c, d, 0.5f * (a * a + c * c + d * d));
    }
}

__global__ __launch_bounds__(BT) void chamfer_kernel() {
    __shared__ int    sbs[NB + 1];
    __shared__ float4 swin[2 * WCAPP];     // pair layout
    __shared__ float4 qbuf[QPB];
    __shared__ float  sdist[QPB];
    __shared__ int    slist[QPB];
    __shared__ float  smin[QPB];
    __shared__ int    scount;
    __shared__ int    wKL[4], wKR[4];
    __shared__ int    wScanLo[4], wScanHi[4];
    __shared__ int    bWinLo, bPairs;

    int blk = blockIdx.x;                 // 1024 blocks
    int dir = blk >> 9;
    int b   = (blk >> 5) & 15;
    int qt  = blk & 31;
    int tid = threadIdx.x;
    int lane = tid & 31;
    int wid  = tid >> 5;

    int qRow  = dir ? (16 + b) : b;
    int dbRow = dir ? b : (16 + b);
    const float4* db = g_sorted + (size_t)dbRow * NP;

    for (int k = tid; k <= NB; k += BT) sbs[k] = g_binstart[dbRow][k];
    if (tid == 0) scount = 0;

    float4 q = g_sorted[(size_t)qRow * NP + qt * QPB + tid];
    qbuf[tid] = q;
    __syncthreads();

    // Per-warp window: span of the warp's 32 queries + PAD, count-extended.
    int myBin = binof(q.x);
    int kL = (int)__reduce_min_sync(FULLM, (unsigned)myBin);
    int kR = (int)__reduce_max_sync(FULLM, (unsigned)myBin);
    kL = max(kL - PAD, 0);
    kR = min(kR + PAD, NB - 1);
    while (sbs[kR + 1] - sbs[kL] < WMIN && (kL > 0 || kR < NB - 1)) {
        if (kL > 0) kL--;
        if (kR < NB - 1) kR++;
    }
    if (lane == 0) { wKL[wid] = kL; wKR[wid] = kR; }
    __syncthreads();

    if (tid == 0) {
        int kLb = min(min(wKL[0], wKL[1]), min(wKL[2], wKL[3]));
        int kRb = max(max(wKR[0], wKR[1]), max(wKR[2], wKR[3]));
        int loE = sbs[kLb] & ~1;                     // even start (<= sbs[kL])
        int cnt = sbs[kRb + 1] - loE;
        int pr  = min((cnt + 1) >> 1, WCAPP);
        pr = min(pr, (NP - loE) >> 1);
        bWinLo = loE;
        bPairs = pr;
    }
    __syncthreads();
    int loE = bWinLo, pairs = bPairs;
    int covEnd = loE + 2 * pairs;

    // Stage pairs (2 LDG.128 + 2 STS.128 each, coalesced-ish).
    for (int k = tid; k < pairs; k += BT) {
        float4 p0 = db[loE + 2 * k];
        float4 p1 = db[loE + 2 * k + 1];
        swin[2 * k]     = make_float4(p0.x, p1.x, p0.y, p1.y);
        swin[2 * k + 1] = make_float4(p0.z, p1.z, p0.w, p1.w);
    }

    // Warp pair sub-range (floor/ceil superset of warp window).
    int pLo = max((sbs[kL] - loE) >> 1, 0);
    int pHi = min((sbs[kR + 1] - loE + 1) >> 1, pairs);
    bool clampedR = (sbs[kR + 1] > covEnd);
    if (lane == 0) { wScanLo[wid] = loE + 2 * pLo; wScanHi[wid] = min(loE + 2 * pHi, covEnd); }
    __syncthreads();

    unsigned long long nqx = bcast2(-q.x), nqy = bcast2(-q.y), nqz = bcast2(-q.z);
    float m0 = 1e30f, m1 = 1e30f, m2 = 1e30f, m3 = 1e30f;

    const ulonglong2* sp = (const ulonglong2*)swin;
    int k = pLo;
    for (; k + 2 <= pHi; k += 2) {
        ulonglong2 A0 = sp[2 * k];
        ulonglong2 B0 = sp[2 * k + 1];
        ulonglong2 A1 = sp[2 * k + 2];
        ulonglong2 B1 = sp[2 * k + 3];
        unsigned long long t0, t1;
        FMA2(t0, B0.x, nqz, B0.y);
        FMA2(t1, B1.x, nqz, B1.y);
        FMA2(t0, A0.y, nqy, t0);
        FMA2(t1, A1.y, nqy, t1);
        FMA2(t0, A0.x, nqx, t0);
        FMA2(t1, A1.x, nqx, t1);
        minacc2(m0, m1, t0);
        minacc2(m2, m3, t1);
    }
    for (; k < pHi; ++k) {
        ulonglong2 A0 = sp[2 * k];
        ulonglong2 B0 = sp[2 * k + 1];
        unsigned long long t0;
        FMA2(t0, B0.x, nqz, B0.y);
        FMA2(t0, A0.y, nqy, t0);
        FMA2(t0, A0.x, nqx, t0);
        minacc2(m0, m1, t0);
    }
    float m = fminf(fminf(m0, m1), fminf(m2, m3));

    // Exact per-lane exclusion bound at warp-window bin edges.
    float thr   = q.w + m;
    float edgeL = LOV + (float)kL * WBIN;
    float edgeR = LOV + (float)(kR + 1) * WBIN;
    float gl = fmaxf(q.x - edgeL, 0.0f);
    float gr = fmaxf(edgeR - q.x, 0.0f);
    bool dL = (kL == 0)      || (0.5f * gl * gl >= thr);
    bool dR = !clampedR && ((kR == NB - 1) || (0.5f * gr * gr >= thr));

    sdist[tid] = sqrtf(1e-6f + fmaxf(2.0f * thr, 0.0f));

    bool need = !(dL && dR);
    unsigned mk = __ballot_sync(FULLM, need);
    int nneed = __popc(mk);
    if (nneed) {
        int base = 0;
        if (lane == 0) base = atomicAdd(&scount, nneed);
        base = __shfl_sync(FULLM, base, 0);
        if (need) {
            int rank = __popc(mk & ((1u << lane) - 1));
            slist[base + rank] = tid;
            smin[base + rank] = m;
        }
    }
    __syncthreads();

    // Block-local exact phase 2: one warp per spilled query; skip scanned range.
    int ns = scount;
    for (int i = wid; i < ns; i += BT / 32) {
        int t = slist[i];
        float mm = smin[i];
        float4 q2 = qbuf[t];
        int w2 = t >> 5;
        int skLo = wScanLo[w2], skHi = wScanHi[w2];

        float d1 = sqrtf(fmaxf(2.0f * (q2.w + mm), 0.0f)) * 1.0005f + 1e-5f;
        int lo2 = sbs[binof(q2.x - d1)];
        int hi2 = sbs[binof(q2.x + d1) + 1];

        int hA = min(hi2, skLo);
        for (int jj = lo2 + lane; jj < hA; jj += 32) {
            float4 p = __ldg(&db[jj]);
            mm = fminf(mm, fmaf(-q2.x, p.x, fmaf(-q2.y, p.y, fmaf(-q2.z, p.z, p.w))));
        }
        int lB = max(lo2, skHi);
        for (int jj = lB + lane; jj < hi2; jj += 32) {
            float4 p = __ldg(&db[jj]);
            mm = fminf(mm, fmaf(-q2.x, p.x, fmaf(-q2.y, p.y, fmaf(-q2.z, p.z, p.w))));
        }
        #pragma unroll
        for (int o = 16; o; o >>= 1)
            mm = fminf(mm, __shfl_xor_sync(FULLM, mm, o));
        if (lane == 0)
            sdist[t] = sqrtf(1e-6f + fmaxf(2.0f * (q2.w + mm), 0.0f));
    }
    __syncthreads();

    #pragma unroll
    for (int st = BT / 2; st > 0; st >>= 1) {
        if (tid < st) sdist[tid] += sdist[tid + st];
        __syncthreads();
    }
    if (tid == 0) g_partial[blk] = sdist[0];
}

__global__ __launch_bounds__(512) void finalize_kernel(float* __restrict__ out) {
    __shared__ float s[512];
    int tid = threadIdx.x;
    s[tid] = g_partial[tid] + g_partial[tid + 512];
    __syncthreads();
    #pragma unroll
    for (int st = 256; st > 0; st >>= 1) {
        if (tid < st) s[tid] += s[tid + st];
        __syncthreads();
    }
    if (tid == 0) out[0] = s[0] * (1.0f / (float)TOTAL);
}

extern "C" void kernel_launch(void* const* d_in, const int* in_sizes, int n_in,
                              void* d_out, int out_size) {
    const float* x = (const float*)d_in[0];
    const float* y = (const float*)d_in[1];
    float* out = (float*)d_out;

    prep_kernel<<<ROWS, 512>>>(x, y);
    chamfer_kernel<<<NBLK, BT>>>();
    finalize_kernel<<<1, 512>>>(out);
}